// round 7
// baseline (speedup 1.0000x reference)
#include <cuda_runtime.h>

// WindowOverlapProcessor: persistent blocks + double-buffered cp.async staging.
// Tile = (b, even row-pair, 256-px w slab) = 66 chunks x 384B staged to smem.
// While computing tile t from buf b, tile t+1 streams into buf b^1
// (commit_group / wait_group 1) -> DRAM latency off the critical path.
// Grid 592 = 148 SM x 4 blocks (smem 2x27.4KB). Conflict-free LDS.128
// (chunk stride 26 float4 = 416B). Boundary windows: clamp-index+zero-weight.

#define HW_      63
#define NW_      (HW_ * HW_)
#define PLANE    (512 * 512)
#define NTILES   4096
#define GRID_    592
#define CHUNK_F4 26
#define BUF_F4   (66 * CHUNK_F4)     // 1716 float4 per buffer
#define SMEM_BYTES (2 * BUF_F4 * 16 + 64)

__global__ void __launch_bounds__(128, 4)
wop_pipe(const float* __restrict__ windows, float* __restrict__ out)
{
    extern __shared__ float4 sm[];
    float4* stage0 = sm;                       // 2 buffers of BUF_F4
    float*  g = (float*)(sm + 2 * BUF_F4);     // 16-entry gaussian

    int tid = threadIdx.x;

    // ---- staging: issue 66 chunks x 24 float4 of `tile` into buffer bsel ----
    auto stage_tile = [&](int tile, int bsel) {
        int wslab = tile & 1;
        int hpair = (tile >> 1) & 255;
        int b     = tile >> 9;
        int h0 = hpair << 1;
        int kh = h0 >> 3;
        int i0cl = max(kh - 1, 0), i1cl = min(kh, HW_ - 1);
        int dA = h0 - (i0cl << 3), dB = h0 - (i1cl << 3);
        int jbase = ((wslab << 8) >> 3) - 1;
        int bNW = b * NW_;
        unsigned sb = (unsigned)__cvta_generic_to_shared(stage0 + bsel * BUF_F4);
        int base0 = (bNW + i0cl * HW_) * 192 + dA * 12;   // float4 units
        int base1 = (bNW + i1cl * HW_) * 192 + dB * 12;

        // i-row 0: smem chunks 0..32
        int c = tid / 24, w = tid - c * 24;
        for (int s = tid; s < 792; s += 128) {
            int j = min(max(jbase + c, 0), HW_ - 1);
            const float4* src = ((const float4*)windows) + (base0 + j * 192 + w);
            unsigned dst = sb + (unsigned)((c * CHUNK_F4 + w) << 4);
            asm volatile("cp.async.cg.shared.global [%0], [%1], 16;"
                         :: "r"(dst), "l"(src) : "memory");
            w += 8; c += 5; if (w >= 24) { w -= 24; ++c; }
        }
        // i-row 1: smem chunks 33..65
        c = tid / 24; w = tid - c * 24;
        for (int s = tid; s < 792; s += 128) {
            int j = min(max(jbase + c, 0), HW_ - 1);
            const float4* src = ((const float4*)windows) + (base1 + j * 192 + w);
            unsigned dst = sb + (unsigned)(((33 + c) * CHUNK_F4 + w) << 4);
            asm volatile("cp.async.cg.shared.global [%0], [%1], 16;"
                         :: "r"(dst), "l"(src) : "memory");
            w += 8; c += 5; if (w >= 24) { w -= 24; ++c; }
        }
        asm volatile("cp.async.commit_group;" ::: "memory");
    };

    // ---- consumer for `tile` from buffer bsel ----
    auto compute_tile = [&](int tile, int bsel) {
        const float4* st = stage0 + bsel * BUF_F4;
        int wslab = tile & 1;
        int hpair = (tile >> 1) & 255;
        int b     = tile >> 9;
        int h0 = hpair << 1;
        int w0 = wslab << 8;
        int kh = h0 >> 3;

        int r     = tid >> 6;
        int w4loc = (tid & 63) << 2;
        int w4 = w0 + w4loc;
        int h  = h0 + r;
        int kw = w4 >> 3;
        int u0 = w4loc >> 3;
        int dwA = (w4 & 7) + 8;        // {8,12}  window kw-1
        int dwB = w4 & 7;              // {0,4}   window kw

        bool vi0 = (kh >= 1),  vi1 = (kh <= HW_ - 1);
        bool vj0 = (kw >= 1),  vj1 = (kw <= HW_ - 1);

        float gh0 = vi0 ? g[(h & 7) + 8] : 0.0f;
        float gh1 = vi1 ? g[h & 7]       : 0.0f;
        float gwA0 = vj0 ? g[dwA]     : 0.0f;
        float gwA1 = vj0 ? g[dwA + 1] : 0.0f;
        float gwA2 = vj0 ? g[dwA + 2] : 0.0f;
        float gwA3 = vj0 ? g[dwA + 3] : 0.0f;
        float gwB0 = vj1 ? g[dwB]     : 0.0f;
        float gwB1 = vj1 ? g[dwB + 1] : 0.0f;
        float gwB2 = vj1 ? g[dwB + 2] : 0.0f;
        float gwB3 = vj1 ? g[dwB + 3] : 0.0f;

        float sh = gh0 + gh1;
        float inv0 = 1.0f / (sh * (gwA0 + gwB0) + 1e-8f);
        float inv1 = 1.0f / (sh * (gwA1 + gwB1) + 1e-8f);
        float inv2 = 1.0f / (sh * (gwA2 + gwB2) + 1e-8f);
        float inv3 = 1.0f / (sh * (gwA3 + gwB3) + 1e-8f);

        int rowoff = r * 12;
        int fA = (dwA * 3) >> 2;       // 6 or 9
        int fB = (dwB * 3) >> 2;       // 0 or 3
        int c00 = (u0)      * CHUNK_F4 + rowoff + fA;
        int c01 = (u0 + 1)  * CHUNK_F4 + rowoff + fB;
        int c10 = (33 + u0) * CHUNK_F4 + rowoff + fA;
        int c11 = (34 + u0) * CHUNK_F4 + rowoff + fB;

        float a00, a01, a02, a10, a11, a12, a20, a21, a22, a30, a31, a32;
        {
            float4 va = st[c00], vb = st[c00 + 1], vc = st[c00 + 2];
            float q0 = gh0 * gwA0, q1 = gh0 * gwA1, q2 = gh0 * gwA2, q3 = gh0 * gwA3;
            a00 = q0 * va.x; a01 = q0 * va.y; a02 = q0 * va.z;
            a10 = q1 * va.w; a11 = q1 * vb.x; a12 = q1 * vb.y;
            a20 = q2 * vb.z; a21 = q2 * vb.w; a22 = q2 * vc.x;
            a30 = q3 * vc.y; a31 = q3 * vc.z; a32 = q3 * vc.w;
        }
        {
            float4 va = st[c01], vb = st[c01 + 1], vc = st[c01 + 2];
            float q0 = gh0 * gwB0, q1 = gh0 * gwB1, q2 = gh0 * gwB2, q3 = gh0 * gwB3;
            a00 += q0 * va.x; a01 += q0 * va.y; a02 += q0 * va.z;
            a10 += q1 * va.w; a11 += q1 * vb.x; a12 += q1 * vb.y;
            a20 += q2 * vb.z; a21 += q2 * vb.w; a22 += q2 * vc.x;
            a30 += q3 * vc.y; a31 += q3 * vc.z; a32 += q3 * vc.w;
        }
        {
            float4 va = st[c10], vb = st[c10 + 1], vc = st[c10 + 2];
            float q0 = gh1 * gwA0, q1 = gh1 * gwA1, q2 = gh1 * gwA2, q3 = gh1 * gwA3;
            a00 += q0 * va.x; a01 += q0 * va.y; a02 += q0 * va.z;
            a10 += q1 * va.w; a11 += q1 * vb.x; a12 += q1 * vb.y;
            a20 += q2 * vb.z; a21 += q2 * vb.w; a22 += q2 * vc.x;
            a30 += q3 * vc.y; a31 += q3 * vc.z; a32 += q3 * vc.w;
        }
        {
            float4 va = st[c11], vb = st[c11 + 1], vc = st[c11 + 2];
            float q0 = gh1 * gwB0, q1 = gh1 * gwB1, q2 = gh1 * gwB2, q3 = gh1 * gwB3;
            a00 += q0 * va.x; a01 += q0 * va.y; a02 += q0 * va.z;
            a10 += q1 * va.w; a11 += q1 * vb.x; a12 += q1 * vb.y;
            a20 += q2 * vb.z; a21 += q2 * vb.w; a22 += q2 * vc.x;
            a30 += q3 * vc.y; a31 += q3 * vc.z; a32 += q3 * vc.w;
        }

        float* ob = out + b * (3 * PLANE) + (h << 9) + w4;
        *(float4*)(ob)             = make_float4(a00 * inv0, a10 * inv1, a20 * inv2, a30 * inv3);
        *(float4*)(ob + PLANE)     = make_float4(a01 * inv0, a11 * inv1, a21 * inv2, a31 * inv3);
        *(float4*)(ob + 2 * PLANE) = make_float4(a02 * inv0, a12 * inv1, a22 * inv2, a32 * inv3);
    };

    // ---- pipeline ----
    int tile = blockIdx.x;                 // < 592 <= NTILES always
    stage_tile(tile, 0);                   // prefetch first tile

    if (tid < 16) { float x = (float)tid - 7.5f; g[tid] = expf(-(x * x) / 32.0f); }
    __syncthreads();
    if (tid == 0) {
        float ssum = 0.0f;
        #pragma unroll
        for (int k = 0; k < 16; k++) ssum += g[k];
        float si = 1.0f / ssum;
        #pragma unroll
        for (int k = 0; k < 16; k++) g[k] *= si;
    }

    int buf = 0;
    int nt = tile + GRID_;
    while (tile < NTILES) {
        bool haveN = (nt < NTILES);
        if (haveN) {
            stage_tile(nt, buf ^ 1);
            asm volatile("cp.async.wait_group 1;" ::: "memory");
        } else {
            asm volatile("cp.async.wait_group 0;" ::: "memory");
        }
        __syncthreads();                    // tile's data visible to all (also g normalize on 1st iter)
        compute_tile(tile, buf);
        __syncthreads();                    // all readers done before buf is re-staged
        tile = nt; nt += GRID_; buf ^= 1;
    }
}

extern "C" void kernel_launch(void* const* d_in, const int* in_sizes, int n_in,
                              void* d_out, int out_size)
{
    const float* windows = (const float*)d_in[0];
    float* out = (float*)d_out;
    cudaFuncSetAttribute(wop_pipe, cudaFuncAttributeMaxDynamicSharedMemorySize, SMEM_BYTES);
    wop_pipe<<<GRID_, 128, SMEM_BYTES>>>(windows, out);
}

// round 8
// speedup vs baseline: 1.0299x; 1.0299x over previous
#include <cuda_runtime.h>

// WindowOverlapProcessor: persistent-lite, single-buffer smem-staged gather.
// Tile = (b, even row-pair, 256-px w slab): 66 chunks x 384B (2 window rows x
// 48 floats, 128B-aligned) staged via cp.async; consumers do conflict-free
// LDS.128 (chunk stride 26 float4 = 416B). Grid = 148*8 = 1184 persistent
// blocks, 3-4 tiles each (stride 1184) -> no tail-wave quantization, gaussian
// built once. DRAM wait per tile hidden by 8-block/SM interleaving (R6 regime).

#define HW_      63
#define NW_      (HW_ * HW_)
#define PLANE    (512 * 512)
#define NTILES   4096
#define GRID_    1184
#define CHUNK_F4 26
#define BUF_F4   (66 * CHUNK_F4)

__global__ void __launch_bounds__(128, 8)
wop_pers(const float* __restrict__ windows, float* __restrict__ out)
{
    __shared__ float4 stage[BUF_F4];     // 27456 B
    __shared__ float  g[16];

    int tid = threadIdx.x;
    unsigned sb = (unsigned)__cvta_generic_to_shared(stage);

    // ---- stage one tile: 2 i-rows x 33 chunks x 24 float4, strength-reduced ----
    auto stage_tile = [&](int tile) {
        int wslab = tile & 1;
        int hpair = (tile >> 1) & 255;
        int b     = tile >> 9;
        int h0 = hpair << 1;
        int kh = h0 >> 3;
        int i0cl = max(kh - 1, 0), i1cl = min(kh, HW_ - 1);
        int dA = h0 - (i0cl << 3), dB = h0 - (i1cl << 3);
        int jbase = (wslab << 5) - 1;               // (w0/8) - 1
        int bNW = b * NW_;
        int base0 = (bNW + i0cl * HW_) * 192 + dA * 12;   // float4 units
        int base1 = (bNW + i1cl * HW_) * 192 + dB * 12;

        // i-row 0 -> chunks 0..32
        int c = tid / 24, w = tid - c * 24;
        #pragma unroll 1
        for (int s = tid; s < 792; s += 128) {
            int j = min(max(jbase + c, 0), HW_ - 1);
            const float4* src = ((const float4*)windows) + (base0 + j * 192 + w);
            unsigned dst = sb + (unsigned)((c * CHUNK_F4 + w) << 4);
            asm volatile("cp.async.cg.shared.global [%0], [%1], 16;"
                         :: "r"(dst), "l"(src) : "memory");
            w += 8; c += 5; if (w >= 24) { w -= 24; ++c; }
        }
        // i-row 1 -> chunks 33..65
        c = tid / 24; w = tid - c * 24;
        #pragma unroll 1
        for (int s = tid; s < 792; s += 128) {
            int j = min(max(jbase + c, 0), HW_ - 1);
            const float4* src = ((const float4*)windows) + (base1 + j * 192 + w);
            unsigned dst = sb + (unsigned)(((33 + c) * CHUNK_F4 + w) << 4);
            asm volatile("cp.async.cg.shared.global [%0], [%1], 16;"
                         :: "r"(dst), "l"(src) : "memory");
            w += 8; c += 5; if (w >= 24) { w -= 24; ++c; }
        }
        asm volatile("cp.async.commit_group;" ::: "memory");
    };

    // ---- consume one tile ----
    auto compute_tile = [&](int tile) {
        int wslab = tile & 1;
        int hpair = (tile >> 1) & 255;
        int b     = tile >> 9;
        int h0 = hpair << 1;
        int w0 = wslab << 8;
        int kh = h0 >> 3;

        int r     = tid >> 6;
        int w4loc = (tid & 63) << 2;
        int w4 = w0 + w4loc;
        int h  = h0 + r;
        int kw = w4 >> 3;
        int u0 = w4loc >> 3;
        int dwA = (w4 & 7) + 8;        // {8,12}  window kw-1
        int dwB = w4 & 7;              // {0,4}   window kw

        bool vi0 = (kh >= 1),  vi1 = (kh <= HW_ - 1);
        bool vj0 = (kw >= 1),  vj1 = (kw <= HW_ - 1);

        float gh0 = vi0 ? g[(h & 7) + 8] : 0.0f;
        float gh1 = vi1 ? g[h & 7]       : 0.0f;
        float gwA0 = vj0 ? g[dwA]     : 0.0f;
        float gwA1 = vj0 ? g[dwA + 1] : 0.0f;
        float gwA2 = vj0 ? g[dwA + 2] : 0.0f;
        float gwA3 = vj0 ? g[dwA + 3] : 0.0f;
        float gwB0 = vj1 ? g[dwB]     : 0.0f;
        float gwB1 = vj1 ? g[dwB + 1] : 0.0f;
        float gwB2 = vj1 ? g[dwB + 2] : 0.0f;
        float gwB3 = vj1 ? g[dwB + 3] : 0.0f;

        float sh = gh0 + gh1;
        float inv0 = 1.0f / (sh * (gwA0 + gwB0) + 1e-8f);
        float inv1 = 1.0f / (sh * (gwA1 + gwB1) + 1e-8f);
        float inv2 = 1.0f / (sh * (gwA2 + gwB2) + 1e-8f);
        float inv3 = 1.0f / (sh * (gwA3 + gwB3) + 1e-8f);

        int rowoff = r * 12;
        int fA = (dwA * 3) >> 2;       // 6 or 9
        int fB = (dwB * 3) >> 2;       // 0 or 3
        int c00 = (u0)      * CHUNK_F4 + rowoff + fA;
        int c01 = (u0 + 1)  * CHUNK_F4 + rowoff + fB;
        int c10 = (33 + u0) * CHUNK_F4 + rowoff + fA;
        int c11 = (34 + u0) * CHUNK_F4 + rowoff + fB;

        float a00, a01, a02, a10, a11, a12, a20, a21, a22, a30, a31, a32;
        {
            float4 va = stage[c00], vb = stage[c00 + 1], vc = stage[c00 + 2];
            float q0 = gh0 * gwA0, q1 = gh0 * gwA1, q2 = gh0 * gwA2, q3 = gh0 * gwA3;
            a00 = q0 * va.x; a01 = q0 * va.y; a02 = q0 * va.z;
            a10 = q1 * va.w; a11 = q1 * vb.x; a12 = q1 * vb.y;
            a20 = q2 * vb.z; a21 = q2 * vb.w; a22 = q2 * vc.x;
            a30 = q3 * vc.y; a31 = q3 * vc.z; a32 = q3 * vc.w;
        }
        {
            float4 va = stage[c01], vb = stage[c01 + 1], vc = stage[c01 + 2];
            float q0 = gh0 * gwB0, q1 = gh0 * gwB1, q2 = gh0 * gwB2, q3 = gh0 * gwB3;
            a00 += q0 * va.x; a01 += q0 * va.y; a02 += q0 * va.z;
            a10 += q1 * va.w; a11 += q1 * vb.x; a12 += q1 * vb.y;
            a20 += q2 * vb.z; a21 += q2 * vb.w; a22 += q2 * vc.x;
            a30 += q3 * vc.y; a31 += q3 * vc.z; a32 += q3 * vc.w;
        }
        {
            float4 va = stage[c10], vb = stage[c10 + 1], vc = stage[c10 + 2];
            float q0 = gh1 * gwA0, q1 = gh1 * gwA1, q2 = gh1 * gwA2, q3 = gh1 * gwA3;
            a00 += q0 * va.x; a01 += q0 * va.y; a02 += q0 * va.z;
            a10 += q1 * va.w; a11 += q1 * vb.x; a12 += q1 * vb.y;
            a20 += q2 * vb.z; a21 += q2 * vb.w; a22 += q2 * vc.x;
            a30 += q3 * vc.y; a31 += q3 * vc.z; a32 += q3 * vc.w;
        }
        {
            float4 va = stage[c11], vb = stage[c11 + 1], vc = stage[c11 + 2];
            float q0 = gh1 * gwB0, q1 = gh1 * gwB1, q2 = gh1 * gwB2, q3 = gh1 * gwB3;
            a00 += q0 * va.x; a01 += q0 * va.y; a02 += q0 * va.z;
            a10 += q1 * va.w; a11 += q1 * vb.x; a12 += q1 * vb.y;
            a20 += q2 * vb.z; a21 += q2 * vb.w; a22 += q2 * vc.x;
            a30 += q3 * vc.y; a31 += q3 * vc.z; a32 += q3 * vc.w;
        }

        float* ob = out + b * (3 * PLANE) + (h << 9) + w4;
        *(float4*)(ob)             = make_float4(a00 * inv0, a10 * inv1, a20 * inv2, a30 * inv3);
        *(float4*)(ob + PLANE)     = make_float4(a01 * inv0, a11 * inv1, a21 * inv2, a31 * inv3);
        *(float4*)(ob + 2 * PLANE) = make_float4(a02 * inv0, a12 * inv1, a22 * inv2, a32 * inv3);
    };

    // ---- persistent loop ----
    int tile = blockIdx.x;
    stage_tile(tile);                           // first tile's loads in flight ASAP

    if (tid < 16) { float x = (float)tid - 7.5f; g[tid] = expf(-(x * x) / 32.0f); }
    __syncthreads();
    if (tid == 0) {
        float ssum = 0.0f;
        #pragma unroll
        for (int k = 0; k < 16; k++) ssum += g[k];
        float si = 1.0f / ssum;
        #pragma unroll
        for (int k = 0; k < 16; k++) g[k] *= si;
    }

    #pragma unroll 1
    while (tile < NTILES) {
        asm volatile("cp.async.wait_group 0;" ::: "memory");
        __syncthreads();                        // data + normalized g visible
        compute_tile(tile);
        tile += GRID_;
        __syncthreads();                        // all readers done before restage
        if (tile < NTILES) stage_tile(tile);
    }
}

extern "C" void kernel_launch(void* const* d_in, const int* in_sizes, int n_in,
                              void* d_out, int out_size)
{
    const float* windows = (const float*)d_in[0];
    float* out = (float*)d_out;
    // prefer max smem carveout so 8 blocks/SM (8 x 27.5 KB) stay resident
    cudaFuncSetAttribute(wop_pers, cudaFuncAttributePreferredSharedMemoryCarveout, 100);
    wop_pers<<<GRID_, 128>>>(windows, out);
}